// round 1
// baseline (speedup 1.0000x reference)
#include <cuda_runtime.h>
#include <math.h>

#define Nn 50000
#define Hh 128
#define Ee 800000
#define NGg 64
#define EPSc 1e-5f

// ---------------- device scratch (static globals; no allocation) ----------------
__device__ int   g_is64;
__device__ int   d_src[Ee];
__device__ int   d_dst[Ee];
__device__ int   d_batch[Nn];
__device__ int   d_deg[Nn];
__device__ float d_dis[Nn];
__device__ int   d_rowptr[Nn + 1];
__device__ int   d_cursor[Nn];
__device__ int   d_col[Ee];
__device__ float d_w[Ee];
__device__ int   d_gcnt[NGg];
__device__ int   d_gstart[NGg + 1];
__device__ float d_gcntf[NGg];
__device__ float d_mean[NGg * Hh];
__device__ float d_var[NGg * Hh];
__device__ float d_HA[(size_t)Nn * Hh];
__device__ float d_HB[(size_t)Nn * Hh];
__device__ float d_T[(size_t)Nn * Hh];
__device__ float d_A[(size_t)Nn * Hh];

// ---------------- preprocessing ----------------

// Detect whether edge_index/batch are int64 or int32. int32 pairs read as
// int64 are >= 2^32 for any nonzero high word (values < 50000), so if the
// first 64 int64 reads are all in [0, N) the data is int64.
__global__ void detect_kernel(const void* ei) {
    if (threadIdx.x == 0 && blockIdx.x == 0) {
        const long long* p = (const long long*)ei;
        int ok = 1;
        for (int i = 0; i < 64; i++) {
            long long v = p[i];
            if (v < 0 || v >= (long long)Nn) ok = 0;
        }
        g_is64 = ok;
    }
}

__global__ void zero_kernel() {
    int i = blockIdx.x * blockDim.x + threadIdx.x;
    if (i < Nn) d_deg[i] = 0;
    if (i < NGg) d_gcnt[i] = 0;
}

__global__ void convert_kernel(const void* ei, const void* bt) {
    int is64 = g_is64;
    int stride = gridDim.x * blockDim.x;
    for (int i = blockIdx.x * blockDim.x + threadIdx.x; i < 2 * Ee; i += stride) {
        int v = is64 ? (int)((const long long*)ei)[i] : ((const int*)ei)[i];
        if (i < Ee) d_src[i] = v; else d_dst[i - Ee] = v;
    }
    for (int i = blockIdx.x * blockDim.x + threadIdx.x; i < Nn; i += stride) {
        int v = is64 ? (int)((const long long*)bt)[i] : ((const int*)bt)[i];
        d_batch[i] = v;
    }
}

__global__ void hist_kernel() {
    int i = blockIdx.x * blockDim.x + threadIdx.x;
    if (i < Ee) atomicAdd(&d_deg[d_dst[i]], 1);
    if (i < Nn) atomicAdd(&d_gcnt[d_batch[i]], 1);
}

__global__ void dis_kernel() {
    int i = blockIdx.x * blockDim.x + threadIdx.x;
    if (i < Nn) d_dis[i] = rsqrtf((float)d_deg[i] + 1.0f);
}

// exclusive prefix sum of d_deg -> d_rowptr, single block of 1024 threads
__global__ void scan_kernel() {
    __shared__ int sh[1024];
    __shared__ int carry;
    int tid = threadIdx.x;
    if (tid == 0) { carry = 0; d_rowptr[0] = 0; }
    __syncthreads();
    for (int base = 0; base < Nn; base += 1024) {
        int v = (base + tid < Nn) ? d_deg[base + tid] : 0;
        sh[tid] = v;
        __syncthreads();
        for (int off = 1; off < 1024; off <<= 1) {
            int t = 0;
            if (tid >= off) t = sh[tid - off];
            __syncthreads();
            if (tid >= off) sh[tid] += t;
            __syncthreads();
        }
        if (base + tid < Nn) d_rowptr[base + tid + 1] = carry + sh[tid];
        __syncthreads();
        if (tid == 0) carry += sh[1023];
        __syncthreads();
    }
}

__global__ void gscan_kernel() {
    if (threadIdx.x == 0 && blockIdx.x == 0) {
        int acc = 0;
        d_gstart[0] = 0;
        for (int g = 0; g < NGg; g++) {
            int c = d_gcnt[g];
            acc += c;
            d_gstart[g + 1] = acc;
            d_gcntf[g] = (c > 0) ? (float)c : 1.0f;
        }
    }
}

__global__ void cursor_kernel() {
    int i = blockIdx.x * blockDim.x + threadIdx.x;
    if (i < Nn) d_cursor[i] = d_rowptr[i];
}

__global__ void scatter_kernel() {
    int i = blockIdx.x * blockDim.x + threadIdx.x;
    if (i >= Ee) return;
    int s = d_src[i], dd = d_dst[i];
    int pos = atomicAdd(&d_cursor[dd], 1);
    d_col[pos] = s;
    d_w[pos] = d_dis[s] * d_dis[dd];
}

// ---------------- dense GEMM: Y[n,128] = X[n,128] @ W[128,128] (+bias,relu) ----
// 256 threads/block, 128 rows/block, 8x8 register micro-tile per thread.
// Both operands staged in SMEM (128 KB dynamic).
template <int FUSE>  // 0: plain, 2: bias + relu
__global__ void gemm_kernel(const float* __restrict__ X, const float* __restrict__ W,
                            const float* __restrict__ bias, float* __restrict__ Y, int n) {
    extern __shared__ float sh[];
    float* Xs = sh;              // transposed: Xs[k*128 + r]
    float* Ws = sh + 128 * 128;  // Ws[k*128 + c]
    int tid = threadIdx.x;
    int row0 = blockIdx.x * 128;

    // load W (coalesced float4)
    const float4* W4 = (const float4*)W;
    float4* Ws4s = (float4*)Ws;
#pragma unroll
    for (int i = 0; i < 16; i++) Ws4s[tid + i * 256] = W4[tid + i * 256];

    // load X tile transposed into Xs
    {
        int lane = tid & 31;    // kq: column group (4 floats)
        int rbase = tid >> 5;   // 0..7
#pragma unroll
        for (int j = 0; j < 16; j++) {
            int r = rbase + j * 8;
            int gr = row0 + r;
            float4 v = make_float4(0.f, 0.f, 0.f, 0.f);
            if (gr < n) v = *(const float4*)&X[(size_t)gr * 128 + lane * 4];
            Xs[(lane * 4 + 0) * 128 + r] = v.x;
            Xs[(lane * 4 + 1) * 128 + r] = v.y;
            Xs[(lane * 4 + 2) * 128 + r] = v.z;
            Xs[(lane * 4 + 3) * 128 + r] = v.w;
        }
    }
    __syncthreads();

    int tx = tid & 15;   // col group: cols tx*8 .. tx*8+7
    int ty = tid >> 4;   // row group: rows ty*8 .. ty*8+7
    float acc[8][8];
#pragma unroll
    for (int i = 0; i < 8; i++)
#pragma unroll
        for (int j = 0; j < 8; j++) acc[i][j] = 0.f;

    const float4* Xs4 = (const float4*)Xs;
    const float4* Ws4 = (const float4*)Ws;
#pragma unroll 4
    for (int k = 0; k < 128; k++) {
        float4 t0 = Xs4[k * 32 + ty * 2];
        float4 t1 = Xs4[k * 32 + ty * 2 + 1];
        float4 u0 = Ws4[k * 32 + tx * 2];
        float4 u1 = Ws4[k * 32 + tx * 2 + 1];
        float a[8] = {t0.x, t0.y, t0.z, t0.w, t1.x, t1.y, t1.z, t1.w};
        float b[8] = {u0.x, u0.y, u0.z, u0.w, u1.x, u1.y, u1.z, u1.w};
#pragma unroll
        for (int i = 0; i < 8; i++)
#pragma unroll
            for (int j = 0; j < 8; j++) acc[i][j] += a[i] * b[j];
    }

    float bv[8];
    if (FUSE == 2) {
#pragma unroll
        for (int j = 0; j < 8; j++) bv[j] = bias[tx * 8 + j];
    }
#pragma unroll
    for (int i = 0; i < 8; i++) {
        int gr = row0 + ty * 8 + i;
        if (gr < n) {
#pragma unroll
            for (int j = 0; j < 8; j += 4) {
                float4 o;
                o.x = acc[i][j + 0]; o.y = acc[i][j + 1];
                o.z = acc[i][j + 2]; o.w = acc[i][j + 3];
                if (FUSE == 2) {
                    o.x = fmaxf(o.x + bv[j + 0], 0.f);
                    o.y = fmaxf(o.y + bv[j + 1], 0.f);
                    o.z = fmaxf(o.z + bv[j + 2], 0.f);
                    o.w = fmaxf(o.w + bv[j + 3], 0.f);
                }
                *(float4*)&Y[(size_t)gr * 128 + tx * 8 + j] = o;
            }
        }
    }
}

// ---------------- CSR aggregation: A[i] = sum_e w_e*T[col_e] + dis_i^2*T[i] + b
__global__ void agg_kernel(const float* __restrict__ T, const float* __restrict__ bias,
                           float* __restrict__ A) {
    int warp = (blockIdx.x * blockDim.x + threadIdx.x) >> 5;
    if (warp >= Nn) return;
    int lane = threadIdx.x & 31;
    int s = d_rowptr[warp], e = d_rowptr[warp + 1];
    float ax = 0.f, ay = 0.f, az = 0.f, aw = 0.f;
    int p = s;
    for (; p + 4 <= e; p += 4) {
        int c0 = d_col[p], c1 = d_col[p + 1], c2 = d_col[p + 2], c3 = d_col[p + 3];
        float w0 = d_w[p], w1 = d_w[p + 1], w2 = d_w[p + 2], w3 = d_w[p + 3];
        float4 v0 = *(const float4*)&T[(size_t)c0 * 128 + lane * 4];
        float4 v1 = *(const float4*)&T[(size_t)c1 * 128 + lane * 4];
        float4 v2 = *(const float4*)&T[(size_t)c2 * 128 + lane * 4];
        float4 v3 = *(const float4*)&T[(size_t)c3 * 128 + lane * 4];
        ax += w0 * v0.x + w1 * v1.x + w2 * v2.x + w3 * v3.x;
        ay += w0 * v0.y + w1 * v1.y + w2 * v2.y + w3 * v3.y;
        az += w0 * v0.z + w1 * v1.z + w2 * v2.z + w3 * v3.z;
        aw += w0 * v0.w + w1 * v1.w + w2 * v2.w + w3 * v3.w;
    }
    for (; p < e; p++) {
        int c = d_col[p];
        float w = d_w[p];
        float4 v = *(const float4*)&T[(size_t)c * 128 + lane * 4];
        ax += w * v.x; ay += w * v.y; az += w * v.z; aw += w * v.w;
    }
    float ds = d_dis[warp];
    float sl = ds * ds;
    float4 tv = *(const float4*)&T[(size_t)warp * 128 + lane * 4];
    float4 bb = *(const float4*)&bias[lane * 4];
    float4 o;
    o.x = ax + sl * tv.x + bb.x;
    o.y = ay + sl * tv.y + bb.y;
    o.z = az + sl * tv.z + bb.z;
    o.w = aw + sl * tv.w + bb.w;
    *(float4*)&A[(size_t)warp * 128 + lane * 4] = o;
}

// ---------------- GraphNorm reductions (batch is sorted -> contiguous ranges) --
__global__ void mean_kernel(const float* __restrict__ A) {
    int g = blockIdx.x;
    int f = blockIdx.y * 32 + (threadIdx.x & 31);
    int sub = threadIdx.x >> 5;  // 0..7
    int s = d_gstart[g], e = d_gstart[g + 1];
    float sum = 0.f;
    for (int i = s + sub; i < e; i += 8) sum += A[(size_t)i * 128 + f];
    __shared__ float sh[8][32];
    sh[sub][threadIdx.x & 31] = sum;
    __syncthreads();
    if (sub == 0) {
        float t = 0.f;
#pragma unroll
        for (int k = 0; k < 8; k++) t += sh[k][threadIdx.x & 31];
        d_mean[g * 128 + f] = t / d_gcntf[g];
    }
}

__global__ void var_kernel(const float* __restrict__ A, const float* __restrict__ alpha) {
    int g = blockIdx.x;
    int f = blockIdx.y * 32 + (threadIdx.x & 31);
    int sub = threadIdx.x >> 5;
    int s = d_gstart[g], e = d_gstart[g + 1];
    float am = alpha[f] * d_mean[g * 128 + f];
    float sum = 0.f;
    for (int i = s + sub; i < e; i += 8) {
        float v = A[(size_t)i * 128 + f] - am;
        sum += v * v;
    }
    __shared__ float sh[8][32];
    sh[sub][threadIdx.x & 31] = sum;
    __syncthreads();
    if (sub == 0) {
        float t = 0.f;
#pragma unroll
        for (int k = 0; k < 8; k++) t += sh[k][threadIdx.x & 31];
        d_var[g * 128 + f] = t / d_gcntf[g];
    }
}

// out = [in +] relu((A - alpha*mean) * rsqrt(var+eps) * gamma + beta)
template <int RES>
__global__ void final_kernel(const float* __restrict__ A, const float* __restrict__ in,
                             const float* __restrict__ alpha, const float* __restrict__ gamma,
                             const float* __restrict__ beta, float* __restrict__ out) {
    int idx = blockIdx.x * blockDim.x + threadIdx.x;  // over N*32 float4s
    if (idx >= Nn * 32) return;
    int node = idx >> 5;
    int q = idx & 31;
    int g = d_batch[node];
    float4 a = ((const float4*)A)[idx];
    float4 m = *(const float4*)&d_mean[g * 128 + q * 4];
    float4 vv = *(const float4*)&d_var[g * 128 + q * 4];
    float4 al = *(const float4*)&alpha[q * 4];
    float4 ga = *(const float4*)&gamma[q * 4];
    float4 be = *(const float4*)&beta[q * 4];
    float4 o;
    o.x = fmaxf((a.x - al.x * m.x) * rsqrtf(vv.x + EPSc) * ga.x + be.x, 0.f);
    o.y = fmaxf((a.y - al.y * m.y) * rsqrtf(vv.y + EPSc) * ga.y + be.y, 0.f);
    o.z = fmaxf((a.z - al.z * m.z) * rsqrtf(vv.z + EPSc) * ga.z + be.z, 0.f);
    o.w = fmaxf((a.w - al.w * m.w) * rsqrtf(vv.w + EPSc) * ga.w + be.w, 0.f);
    if (RES) {
        float4 r = ((const float4*)in)[idx];
        o.x += r.x; o.y += r.y; o.z += r.z; o.w += r.w;
    }
    ((float4*)out)[idx] = o;
}

// ---------------- predictor head: out = sigmoid(P @ Wp2 + bp2) ----------------
__global__ void head_kernel(const float* __restrict__ P, const float* __restrict__ Wp2,
                            const float* __restrict__ bp2, float* __restrict__ out) {
    int warp = (blockIdx.x * blockDim.x + threadIdx.x) >> 5;
    if (warp >= Nn) return;
    int lane = threadIdx.x & 31;
    float4 p = ((const float4*)P)[warp * 32 + lane];
    float4 w = ((const float4*)Wp2)[lane];
    float s = p.x * w.x + p.y * w.y + p.z * w.z + p.w * w.w;
#pragma unroll
    for (int off = 16; off > 0; off >>= 1) s += __shfl_xor_sync(0xffffffffu, s, off);
    if (lane == 0) {
        float z = s + bp2[0];
        out[warp] = 1.f / (1.f + expf(-z));
    }
}

// ---------------- host orchestration ----------------
extern "C" void kernel_launch(void* const* d_in, const int* in_sizes, int n_in,
                              void* d_out, int out_size) {
    const float* x   = (const float*)d_in[0];
    const void*  ei  = d_in[1];
    const void*  bt  = d_in[2];
    const float* W1  = (const float*)d_in[3];
    const float* b1  = (const float*)d_in[4];
    const float* a1  = (const float*)d_in[5];
    const float* g1  = (const float*)d_in[6];
    const float* be1 = (const float*)d_in[7];
    const float* Wm  = (const float*)d_in[8];
    const float* bm  = (const float*)d_in[9];
    const float* am  = (const float*)d_in[10];
    const float* gm  = (const float*)d_in[11];
    const float* bem = (const float*)d_in[12];
    const float* WL  = (const float*)d_in[13];
    const float* bL  = (const float*)d_in[14];
    const float* aL  = (const float*)d_in[15];
    const float* gL  = (const float*)d_in[16];
    const float* beL = (const float*)d_in[17];
    const float* Wp1 = (const float*)d_in[18];
    const float* bp1 = (const float*)d_in[19];
    const float* Wp2 = (const float*)d_in[20];
    const float* bp2 = (const float*)d_in[21];
    float* out = (float*)d_out;

    float *HA, *HB, *T, *A;
    cudaGetSymbolAddress((void**)&HA, d_HA);
    cudaGetSymbolAddress((void**)&HB, d_HB);
    cudaGetSymbolAddress((void**)&T,  d_T);
    cudaGetSymbolAddress((void**)&A,  d_A);

    const size_t smem = 2 * 128 * 128 * sizeof(float);
    cudaFuncSetAttribute(gemm_kernel<0>, cudaFuncAttributeMaxDynamicSharedMemorySize, (int)smem);
    cudaFuncSetAttribute(gemm_kernel<2>, cudaFuncAttributeMaxDynamicSharedMemorySize, (int)smem);

    // ---- preprocessing ----
    detect_kernel<<<1, 32>>>(ei);
    zero_kernel<<<(Nn + 255) / 256, 256>>>();
    convert_kernel<<<1024, 256>>>(ei, bt);
    hist_kernel<<<(Ee + 255) / 256, 256>>>();
    dis_kernel<<<(Nn + 255) / 256, 256>>>();
    scan_kernel<<<1, 1024>>>();
    gscan_kernel<<<1, 32>>>();
    cursor_kernel<<<(Nn + 255) / 256, 256>>>();
    scatter_kernel<<<(Ee + 255) / 256, 256>>>();

    const int gemm_grid = (Nn + 127) / 128;
    const int agg_grid  = (Nn * 32 + 255) / 256;
    const int elem_grid = (Nn * 32 + 255) / 256;
    dim3 red_grid(NGg, 4);

    // ---- layer 1: x -> HB ----
    gemm_kernel<0><<<gemm_grid, 256, smem>>>(x, W1, nullptr, T, Nn);
    agg_kernel<<<agg_grid, 256>>>(T, b1, A);
    mean_kernel<<<red_grid, 256>>>(A);
    var_kernel<<<red_grid, 256>>>(A, a1);
    final_kernel<0><<<elem_grid, 256>>>(A, nullptr, a1, g1, be1, HB);

    // ---- mid layer 0 (residual): HB -> HA ----
    gemm_kernel<0><<<gemm_grid, 256, smem>>>(HB, Wm + 0 * 128 * 128, nullptr, T, Nn);
    agg_kernel<<<agg_grid, 256>>>(T, bm + 0 * 128, A);
    mean_kernel<<<red_grid, 256>>>(A);
    var_kernel<<<red_grid, 256>>>(A, am + 0 * 128);
    final_kernel<1><<<elem_grid, 256>>>(A, HB, am + 0 * 128, gm + 0 * 128, bem + 0 * 128, HA);

    // ---- mid layer 1 (residual): HA -> HB ----
    gemm_kernel<0><<<gemm_grid, 256, smem>>>(HA, Wm + 1 * 128 * 128, nullptr, T, Nn);
    agg_kernel<<<agg_grid, 256>>>(T, bm + 1 * 128, A);
    mean_kernel<<<red_grid, 256>>>(A);
    var_kernel<<<red_grid, 256>>>(A, am + 1 * 128);
    final_kernel<1><<<elem_grid, 256>>>(A, HA, am + 1 * 128, gm + 1 * 128, bem + 1 * 128, HB);

    // ---- last layer: HB -> HA ----
    gemm_kernel<0><<<gemm_grid, 256, smem>>>(HB, WL, nullptr, T, Nn);
    agg_kernel<<<agg_grid, 256>>>(T, bL, A);
    mean_kernel<<<red_grid, 256>>>(A);
    var_kernel<<<red_grid, 256>>>(A, aL);
    final_kernel<0><<<elem_grid, 256>>>(A, nullptr, aL, gL, beL, HA);

    // ---- predictor: HA -> T (relu MLP) -> out ----
    gemm_kernel<2><<<gemm_grid, 256, smem>>>(HA, Wp1, bp1, T, Nn);
    head_kernel<<<agg_grid, 256>>>(T, Wp2, bp2, out);
}

// round 2
// speedup vs baseline: 1.3471x; 1.3471x over previous
#include <cuda_runtime.h>
#include <cuda_fp16.h>
#include <math.h>

#define Nn 50000
#define Hh 128
#define Ee 800000
#define NGg 64
#define EPSc 1e-5f
#define NB_SCAN 196   // ceil(50000/256)

// ---------------- device scratch (static globals; no allocation) ----------------
__device__ int    g_is64;
__device__ int    d_src[Ee];
__device__ int    d_dst[Ee];
__device__ int    d_batch[Nn];
__device__ int    d_deg[Nn];
__device__ float  d_dis[Nn];
__device__ int    d_rowptr[Nn + 1];
__device__ int    d_cursor[Nn];
__device__ int    d_col[Ee];
__device__ float  d_w[Ee];
__device__ int    d_bsum[NB_SCAN];
__device__ int    d_boff[NB_SCAN];
__device__ int    d_gstart[NGg + 1];
__device__ float  d_gcntf[NGg];
__device__ float  d_mean[NGg * Hh];
__device__ float  d_var[NGg * Hh];
__device__ float  d_HA[(size_t)Nn * Hh];
__device__ float  d_HB[(size_t)Nn * Hh];
__device__ __half d_Th[(size_t)Nn * Hh];
__device__ float  d_A[(size_t)Nn * Hh];

// ---------------- preprocessing ----------------

// Detect whether edge_index/batch are int64 or int32.
__global__ void detect_kernel(const void* ei) {
    if (threadIdx.x == 0 && blockIdx.x == 0) {
        const long long* p = (const long long*)ei;
        int ok = 1;
        for (int i = 0; i < 64; i++) {
            long long v = p[i];
            if (v < 0 || v >= (long long)Nn) ok = 0;
        }
        g_is64 = ok;
    }
}

__global__ void zero_kernel() {
    int i = blockIdx.x * blockDim.x + threadIdx.x;
    if (i < Nn) d_deg[i] = 0;
}

// fused: convert edge_index + batch to int32, histogram dst degrees
__global__ void convert_hist_kernel(const void* ei, const void* bt) {
    int is64 = g_is64;
    int stride = gridDim.x * blockDim.x;
    for (int i = blockIdx.x * blockDim.x + threadIdx.x; i < 2 * Ee; i += stride) {
        int v = is64 ? (int)((const long long*)ei)[i] : ((const int*)ei)[i];
        if (i < Ee) d_src[i] = v;
        else { d_dst[i - Ee] = v; atomicAdd(&d_deg[v], 1); }
    }
    for (int i = blockIdx.x * blockDim.x + threadIdx.x; i < Nn; i += stride) {
        int v = is64 ? (int)((const long long*)bt)[i] : ((const int*)bt)[i];
        d_batch[i] = v;
    }
}

// ---- multi-block exclusive scan of d_deg -> d_rowptr ----
__global__ void bsum_kernel() {
    int idx = blockIdx.x * 256 + threadIdx.x;
    int v = (idx < Nn) ? d_deg[idx] : 0;
#pragma unroll
    for (int off = 16; off > 0; off >>= 1) v += __shfl_xor_sync(0xffffffffu, v, off);
    __shared__ int sh[8];
    if ((threadIdx.x & 31) == 0) sh[threadIdx.x >> 5] = v;
    __syncthreads();
    if (threadIdx.x == 0) {
        int t = 0;
#pragma unroll
        for (int k = 0; k < 8; k++) t += sh[k];
        d_bsum[blockIdx.x] = t;
    }
}

__global__ void bscan_kernel() {
    __shared__ int sh[256];
    int t = threadIdx.x;
    sh[t] = (t < NB_SCAN) ? d_bsum[t] : 0;
    __syncthreads();
    for (int off = 1; off < 256; off <<= 1) {
        int v = 0;
        if (t >= off) v = sh[t - off];
        __syncthreads();
        if (t >= off) sh[t] += v;
        __syncthreads();
    }
    if (t < NB_SCAN) d_boff[t] = (t == 0) ? 0 : sh[t - 1];
}

__global__ void rowptr_kernel() {
    __shared__ int sh[256];
    int t = threadIdx.x;
    int idx = blockIdx.x * 256 + t;
    int v = (idx < Nn) ? d_deg[idx] : 0;
    sh[t] = v;
    __syncthreads();
    for (int off = 1; off < 256; off <<= 1) {
        int u = 0;
        if (t >= off) u = sh[t - off];
        __syncthreads();
        if (t >= off) sh[t] += u;
        __syncthreads();
    }
    if (idx < Nn) d_rowptr[idx + 1] = d_boff[blockIdx.x] + sh[t];
    if (idx == 0) d_rowptr[0] = 0;
}

// per-graph node ranges via binary search on sorted batch (no atomics)
__global__ void gstart_kernel() {
    int t = threadIdx.x;
    if (t <= NGg) {
        int lo = 0, hi = Nn;
        while (lo < hi) {
            int mid = (lo + hi) >> 1;
            if (d_batch[mid] < t) lo = mid + 1; else hi = mid;
        }
        d_gstart[t] = lo;
    }
    __syncthreads();
    if (t < NGg) {
        int c = d_gstart[t + 1] - d_gstart[t];
        d_gcntf[t] = (c > 0) ? (float)c : 1.0f;
    }
}

__global__ void dis_cursor_kernel() {
    int i = blockIdx.x * blockDim.x + threadIdx.x;
    if (i < Nn) {
        d_dis[i] = rsqrtf((float)d_deg[i] + 1.0f);
        d_cursor[i] = d_rowptr[i];
    }
}

__global__ void scatter_kernel() {
    int i = blockIdx.x * blockDim.x + threadIdx.x;
    if (i >= Ee) return;
    int s = d_src[i], dd = d_dst[i];
    int pos = atomicAdd(&d_cursor[dd], 1);
    d_col[pos] = s;
    d_w[pos] = d_dis[s] * d_dis[dd];
}

// ---------------- dense GEMM core (macro-shared body) ----------------
// 256 threads/block, 128 rows/block, 8x8 micro-tile. X and W staged in 128KB smem.
#define GEMM_PROLOGUE()                                                          \
    extern __shared__ float sh[];                                                \
    float* Xs = sh;                                                              \
    float* Ws = sh + 128 * 128;                                                  \
    int tid = threadIdx.x;                                                       \
    int row0 = blockIdx.x * 128;                                                 \
    {                                                                            \
        const float4* W4 = (const float4*)W;                                     \
        float4* Ws4s = (float4*)Ws;                                              \
        _Pragma("unroll")                                                        \
        for (int i = 0; i < 16; i++) Ws4s[tid + i * 256] = W4[tid + i * 256];    \
        int lane = tid & 31;                                                     \
        int rbase = tid >> 5;                                                    \
        _Pragma("unroll")                                                        \
        for (int j = 0; j < 16; j++) {                                           \
            int r = rbase + j * 8;                                               \
            int gr = row0 + r;                                                   \
            float4 v = make_float4(0.f, 0.f, 0.f, 0.f);                          \
            if (gr < n) v = *(const float4*)&X[(size_t)gr * 128 + lane * 4];     \
            Xs[(lane * 4 + 0) * 128 + r] = v.x;                                  \
            Xs[(lane * 4 + 1) * 128 + r] = v.y;                                  \
            Xs[(lane * 4 + 2) * 128 + r] = v.z;                                  \
            Xs[(lane * 4 + 3) * 128 + r] = v.w;                                  \
        }                                                                        \
    }                                                                            \
    __syncthreads();                                                             \
    int tx = tid & 15;                                                           \
    int ty = tid >> 4;                                                           \
    float acc[8][8];                                                             \
    _Pragma("unroll")                                                            \
    for (int i = 0; i < 8; i++)                                                  \
        _Pragma("unroll")                                                        \
        for (int j = 0; j < 8; j++) acc[i][j] = 0.f;                             \
    {                                                                            \
        const float4* Xs4 = (const float4*)Xs;                                   \
        const float4* Ws4 = (const float4*)Ws;                                   \
        _Pragma("unroll 4")                                                      \
        for (int k = 0; k < 128; k++) {                                          \
            float4 t0 = Xs4[k * 32 + ty * 2];                                    \
            float4 t1 = Xs4[k * 32 + ty * 2 + 1];                                \
            float4 u0 = Ws4[k * 32 + tx * 2];                                    \
            float4 u1 = Ws4[k * 32 + tx * 2 + 1];                                \
            float a[8] = {t0.x, t0.y, t0.z, t0.w, t1.x, t1.y, t1.z, t1.w};       \
            float b[8] = {u0.x, u0.y, u0.z, u0.w, u1.x, u1.y, u1.z, u1.w};       \
            _Pragma("unroll")                                                    \
            for (int i = 0; i < 8; i++)                                          \
                _Pragma("unroll")                                                \
                for (int j = 0; j < 8; j++) acc[i][j] += a[i] * b[j];            \
        }                                                                        \
    }

// GEMM writing fp16 output (feeds the edge gather)
__global__ __launch_bounds__(256) void gemm_half_kernel(
    const float* __restrict__ X, const float* __restrict__ W,
    __half* __restrict__ Y, int n) {
    GEMM_PROLOGUE()
#pragma unroll
    for (int i = 0; i < 8; i++) {
        int gr = row0 + ty * 8 + i;
        if (gr < n) {
            union { __half2 h[4]; uint4 u; } pk;
#pragma unroll
            for (int j = 0; j < 4; j++)
                pk.h[j] = __floats2half2_rn(acc[i][2 * j], acc[i][2 * j + 1]);
            *(uint4*)&Y[(size_t)gr * 128 + tx * 8] = pk.u;
        }
    }
}

// final GEMM with fused predictor head:
// out[r] = sigmoid( sum_c relu(acc[r][c]+bp1[c]) * Wp2[c] + bp2 )
__global__ __launch_bounds__(256) void gemm_head_kernel(
    const float* __restrict__ X, const float* __restrict__ W,
    const float* __restrict__ bp1, const float* __restrict__ Wp2,
    const float* __restrict__ bp2, float* __restrict__ out, int n) {
    GEMM_PROLOGUE()
    __shared__ float rsum[128 * 16];
    float bv[8], wv[8];
#pragma unroll
    for (int j = 0; j < 8; j++) { bv[j] = bp1[tx * 8 + j]; wv[j] = Wp2[tx * 8 + j]; }
#pragma unroll
    for (int i = 0; i < 8; i++) {
        float p = 0.f;
#pragma unroll
        for (int j = 0; j < 8; j++) {
            float v = fmaxf(acc[i][j] + bv[j], 0.f);
            p += v * wv[j];
        }
        rsum[(ty * 8 + i) * 16 + tx] = p;
    }
    __syncthreads();
    if (tid < 128) {
        int gr = row0 + tid;
        if (gr < n) {
            float s = 0.f;
#pragma unroll
            for (int t = 0; t < 16; t++) s += rsum[tid * 16 + t];
            float z = s + bp2[0];
            out[gr] = 1.f / (1.f + expf(-z));
        }
    }
}

// ---------------- CSR aggregation (fp16 gather, fp32 accumulate) --------------
__global__ void agg_kernel(const __half* __restrict__ T, const float* __restrict__ bias,
                           float* __restrict__ A) {
    int warp = (blockIdx.x * blockDim.x + threadIdx.x) >> 5;
    if (warp >= Nn) return;
    int lane = threadIdx.x & 31;
    int s = d_rowptr[warp], e = d_rowptr[warp + 1];
    float ax = 0.f, ay = 0.f, az = 0.f, aw = 0.f;
    int p = s;
    for (; p + 4 <= e; p += 4) {
        int c0 = d_col[p], c1 = d_col[p + 1], c2 = d_col[p + 2], c3 = d_col[p + 3];
        float w0 = d_w[p], w1 = d_w[p + 1], w2 = d_w[p + 2], w3 = d_w[p + 3];
        uint2 u0 = ((const uint2*)(T + (size_t)c0 * 128))[lane];
        uint2 u1 = ((const uint2*)(T + (size_t)c1 * 128))[lane];
        uint2 u2 = ((const uint2*)(T + (size_t)c2 * 128))[lane];
        uint2 u3 = ((const uint2*)(T + (size_t)c3 * 128))[lane];
        float2 a0 = __half22float2(*(__half2*)&u0.x), b0 = __half22float2(*(__half2*)&u0.y);
        float2 a1 = __half22float2(*(__half2*)&u1.x), b1 = __half22float2(*(__half2*)&u1.y);
        float2 a2 = __half22float2(*(__half2*)&u2.x), b2 = __half22float2(*(__half2*)&u2.y);
        float2 a3 = __half22float2(*(__half2*)&u3.x), b3 = __half22float2(*(__half2*)&u3.y);
        ax += w0 * a0.x + w1 * a1.x + w2 * a2.x + w3 * a3.x;
        ay += w0 * a0.y + w1 * a1.y + w2 * a2.y + w3 * a3.y;
        az += w0 * b0.x + w1 * b1.x + w2 * b2.x + w3 * b3.x;
        aw += w0 * b0.y + w1 * b1.y + w2 * b2.y + w3 * b3.y;
    }
    for (; p < e; p++) {
        int c = d_col[p];
        float w = d_w[p];
        uint2 u = ((const uint2*)(T + (size_t)c * 128))[lane];
        float2 a = __half22float2(*(__half2*)&u.x), b = __half22float2(*(__half2*)&u.y);
        ax += w * a.x; ay += w * a.y; az += w * b.x; aw += w * b.y;
    }
    float ds = d_dis[warp];
    float sl = ds * ds;
    uint2 ut = ((const uint2*)(T + (size_t)warp * 128))[lane];
    float2 ta = __half22float2(*(__half2*)&ut.x), tb = __half22float2(*(__half2*)&ut.y);
    float4 bb = *(const float4*)&bias[lane * 4];
    float4 o;
    o.x = ax + sl * ta.x + bb.x;
    o.y = ay + sl * ta.y + bb.y;
    o.z = az + sl * tb.x + bb.z;
    o.w = aw + sl * tb.y + bb.w;
    *(float4*)&A[(size_t)warp * 128 + lane * 4] = o;
}

// ---------------- GraphNorm: single-pass sum + sumsq reduction ----------------
// var = E[x^2] - m^2 * alpha * (2 - alpha)   with m = E[x]
__global__ void reduce_kernel(const float* __restrict__ A, const float* __restrict__ alpha) {
    int g = blockIdx.x;
    int lane = threadIdx.x & 31;
    int f = blockIdx.y * 32 + lane;
    int sub = threadIdx.x >> 5;  // 0..7
    int s = d_gstart[g], e = d_gstart[g + 1];
    float sum = 0.f, sq = 0.f;
    for (int i = s + sub; i < e; i += 8) {
        float v = A[(size_t)i * 128 + f];
        sum += v; sq += v * v;
    }
    __shared__ float sh1[8][32], sh2[8][32];
    sh1[sub][lane] = sum;
    sh2[sub][lane] = sq;
    __syncthreads();
    if (sub == 0) {
        float t1 = 0.f, t2 = 0.f;
#pragma unroll
        for (int k = 0; k < 8; k++) { t1 += sh1[k][lane]; t2 += sh2[k][lane]; }
        float inv = 1.f / d_gcntf[g];
        float m = t1 * inv;
        float q = t2 * inv;
        float al = alpha[f];
        d_mean[g * 128 + f] = m;
        d_var[g * 128 + f] = q - m * m * al * (2.f - al);
    }
}

// out = [in +] relu((A - alpha*mean) * rsqrt(var+eps) * gamma + beta)
template <int RES>
__global__ void final_kernel(const float* __restrict__ A, const float* __restrict__ in,
                             const float* __restrict__ alpha, const float* __restrict__ gamma,
                             const float* __restrict__ beta, float* __restrict__ out) {
    int idx = blockIdx.x * blockDim.x + threadIdx.x;  // over N*32 float4s
    if (idx >= Nn * 32) return;
    int node = idx >> 5;
    int q = idx & 31;
    int g = d_batch[node];
    float4 a = ((const float4*)A)[idx];
    float4 m = *(const float4*)&d_mean[g * 128 + q * 4];
    float4 vv = *(const float4*)&d_var[g * 128 + q * 4];
    float4 al = *(const float4*)&alpha[q * 4];
    float4 ga = *(const float4*)&gamma[q * 4];
    float4 be = *(const float4*)&beta[q * 4];
    float4 o;
    o.x = fmaxf((a.x - al.x * m.x) * rsqrtf(vv.x + EPSc) * ga.x + be.x, 0.f);
    o.y = fmaxf((a.y - al.y * m.y) * rsqrtf(vv.y + EPSc) * ga.y + be.y, 0.f);
    o.z = fmaxf((a.z - al.z * m.z) * rsqrtf(vv.z + EPSc) * ga.z + be.z, 0.f);
    o.w = fmaxf((a.w - al.w * m.w) * rsqrtf(vv.w + EPSc) * ga.w + be.w, 0.f);
    if (RES) {
        float4 r = ((const float4*)in)[idx];
        o.x += r.x; o.y += r.y; o.z += r.z; o.w += r.w;
    }
    ((float4*)out)[idx] = o;
}

// ---------------- host orchestration ----------------
extern "C" void kernel_launch(void* const* d_in, const int* in_sizes, int n_in,
                              void* d_out, int out_size) {
    const float* x   = (const float*)d_in[0];
    const void*  ei  = d_in[1];
    const void*  bt  = d_in[2];
    const float* W1  = (const float*)d_in[3];
    const float* b1  = (const float*)d_in[4];
    const float* a1  = (const float*)d_in[5];
    const float* g1  = (const float*)d_in[6];
    const float* be1 = (const float*)d_in[7];
    const float* Wm  = (const float*)d_in[8];
    const float* bm  = (const float*)d_in[9];
    const float* am  = (const float*)d_in[10];
    const float* gm  = (const float*)d_in[11];
    const float* bem = (const float*)d_in[12];
    const float* WL  = (const float*)d_in[13];
    const float* bL  = (const float*)d_in[14];
    const float* aL  = (const float*)d_in[15];
    const float* gL  = (const float*)d_in[16];
    const float* beL = (const float*)d_in[17];
    const float* Wp1 = (const float*)d_in[18];
    const float* bp1 = (const float*)d_in[19];
    const float* Wp2 = (const float*)d_in[20];
    const float* bp2 = (const float*)d_in[21];
    float* out = (float*)d_out;

    float *HA, *HB, *A;
    __half* Th;
    cudaGetSymbolAddress((void**)&HA, d_HA);
    cudaGetSymbolAddress((void**)&HB, d_HB);
    cudaGetSymbolAddress((void**)&Th, d_Th);
    cudaGetSymbolAddress((void**)&A,  d_A);

    const size_t smem = 2 * 128 * 128 * sizeof(float);
    cudaFuncSetAttribute(gemm_half_kernel, cudaFuncAttributeMaxDynamicSharedMemorySize, (int)smem);
    cudaFuncSetAttribute(gemm_head_kernel, cudaFuncAttributeMaxDynamicSharedMemorySize, (int)smem);

    // ---- preprocessing ----
    detect_kernel<<<1, 32>>>(ei);
    zero_kernel<<<(Nn + 255) / 256, 256>>>();
    convert_hist_kernel<<<1024, 256>>>(ei, bt);
    bsum_kernel<<<NB_SCAN, 256>>>();
    bscan_kernel<<<1, 256>>>();
    rowptr_kernel<<<NB_SCAN, 256>>>();
    gstart_kernel<<<1, 128>>>();
    dis_cursor_kernel<<<(Nn + 255) / 256, 256>>>();
    scatter_kernel<<<(Ee + 255) / 256, 256>>>();

    const int gemm_grid = (Nn + 127) / 128;
    const int agg_grid  = (Nn * 32 + 255) / 256;
    const int elem_grid = (Nn * 32 + 255) / 256;
    dim3 red_grid(NGg, 4);

    // ---- layer 1: x -> HB ----
    gemm_half_kernel<<<gemm_grid, 256, smem>>>(x, W1, Th, Nn);
    agg_kernel<<<agg_grid, 256>>>(Th, b1, A);
    reduce_kernel<<<red_grid, 256>>>(A, a1);
    final_kernel<0><<<elem_grid, 256>>>(A, nullptr, a1, g1, be1, HB);

    // ---- mid layer 0 (residual): HB -> HA ----
    gemm_half_kernel<<<gemm_grid, 256, smem>>>(HB, Wm + 0 * 128 * 128, Th, Nn);
    agg_kernel<<<agg_grid, 256>>>(Th, bm + 0 * 128, A);
    reduce_kernel<<<red_grid, 256>>>(A, am + 0 * 128);
    final_kernel<1><<<elem_grid, 256>>>(A, HB, am + 0 * 128, gm + 0 * 128, bem + 0 * 128, HA);

    // ---- mid layer 1 (residual): HA -> HB ----
    gemm_half_kernel<<<gemm_grid, 256, smem>>>(HA, Wm + 1 * 128 * 128, Th, Nn);
    agg_kernel<<<agg_grid, 256>>>(Th, bm + 1 * 128, A);
    reduce_kernel<<<red_grid, 256>>>(A, am + 1 * 128);
    final_kernel<1><<<elem_grid, 256>>>(A, HA, am + 1 * 128, gm + 1 * 128, bem + 1 * 128, HB);

    // ---- last layer: HB -> HA ----
    gemm_half_kernel<<<gemm_grid, 256, smem>>>(HB, WL, Th, Nn);
    agg_kernel<<<agg_grid, 256>>>(Th, bL, A);
    reduce_kernel<<<red_grid, 256>>>(A, aL);
    final_kernel<0><<<elem_grid, 256>>>(A, nullptr, aL, gL, beL, HA);

    // ---- predictor: HA -> out (GEMM with fused relu-MLP head) ----
    gemm_head_kernel<<<gemm_grid, 256, smem>>>(HA, Wp1, bp1, Wp2, bp2, out, Nn);
}

// round 3
// speedup vs baseline: 2.0108x; 1.4927x over previous
#include <cuda_runtime.h>
#include <cuda_fp16.h>
#include <math.h>

#define Nn 50000
#define Hh 128
#define Ee 800000
#define NGg 64
#define EPSc 1e-5f
#define NB_SCAN 196   // ceil(50000/256)

// ---------------- device scratch (static globals; no allocation) ----------------
__device__ int    g_is64;
__device__ int    d_src[Ee];
__device__ int    d_dst[Ee];
__device__ int    d_batch[Nn];
__device__ int    d_deg[Nn];
__device__ float  d_dis[Nn];
__device__ int    d_rowptr[Nn + 1];
__device__ int    d_cursor[Nn];
__device__ int    d_col[Ee];
__device__ float  d_w[Ee];
__device__ int    d_bsum[NB_SCAN];
__device__ int    d_boff[NB_SCAN];
__device__ int    d_gstart[NGg + 1];
__device__ float  d_gcntf[NGg];
__device__ float  d_mean[NGg * Hh];
__device__ float  d_var[NGg * Hh];
__device__ float  d_HA[(size_t)Nn * Hh];
__device__ float  d_HB[(size_t)Nn * Hh];
__device__ __half d_Th[(size_t)Nn * Hh];
__device__ float  d_A[(size_t)Nn * Hh];

// ---------------- preprocessing ----------------

__global__ void detect_kernel(const void* ei) {
    if (threadIdx.x == 0 && blockIdx.x == 0) {
        const long long* p = (const long long*)ei;
        int ok = 1;
        for (int i = 0; i < 64; i++) {
            long long v = p[i];
            if (v < 0 || v >= (long long)Nn) ok = 0;
        }
        g_is64 = ok;
    }
}

__global__ void zero_kernel() {
    int i = blockIdx.x * blockDim.x + threadIdx.x;
    if (i < Nn) d_deg[i] = 0;
}

// fused: convert edge_index + batch to int32, histogram dst degrees
__global__ void convert_hist_kernel(const void* ei, const void* bt) {
    int is64 = g_is64;
    int stride = gridDim.x * blockDim.x;
    for (int i = blockIdx.x * blockDim.x + threadIdx.x; i < 2 * Ee; i += stride) {
        int v = is64 ? (int)((const long long*)ei)[i] : ((const int*)ei)[i];
        if (i < Ee) d_src[i] = v;
        else { d_dst[i - Ee] = v; atomicAdd(&d_deg[v], 1); }
    }
    for (int i = blockIdx.x * blockDim.x + threadIdx.x; i < Nn; i += stride) {
        int v = is64 ? (int)((const long long*)bt)[i] : ((const int*)bt)[i];
        d_batch[i] = v;
    }
}

// ---- multi-block exclusive scan of d_deg -> d_rowptr ----
__global__ void bsum_kernel() {
    int idx = blockIdx.x * 256 + threadIdx.x;
    int v = (idx < Nn) ? d_deg[idx] : 0;
#pragma unroll
    for (int off = 16; off > 0; off >>= 1) v += __shfl_xor_sync(0xffffffffu, v, off);
    __shared__ int sh[8];
    if ((threadIdx.x & 31) == 0) sh[threadIdx.x >> 5] = v;
    __syncthreads();
    if (threadIdx.x == 0) {
        int t = 0;
#pragma unroll
        for (int k = 0; k < 8; k++) t += sh[k];
        d_bsum[blockIdx.x] = t;
    }
}

__global__ void bscan_kernel() {
    __shared__ int sh[256];
    int t = threadIdx.x;
    sh[t] = (t < NB_SCAN) ? d_bsum[t] : 0;
    __syncthreads();
    for (int off = 1; off < 256; off <<= 1) {
        int v = 0;
        if (t >= off) v = sh[t - off];
        __syncthreads();
        if (t >= off) sh[t] += v;
        __syncthreads();
    }
    if (t < NB_SCAN) d_boff[t] = (t == 0) ? 0 : sh[t - 1];
}

__global__ void rowptr_kernel() {
    __shared__ int sh[256];
    int t = threadIdx.x;
    int idx = blockIdx.x * 256 + t;
    int v = (idx < Nn) ? d_deg[idx] : 0;
    sh[t] = v;
    __syncthreads();
    for (int off = 1; off < 256; off <<= 1) {
        int u = 0;
        if (t >= off) u = sh[t - off];
        __syncthreads();
        if (t >= off) sh[t] += u;
        __syncthreads();
    }
    if (idx < Nn) d_rowptr[idx + 1] = d_boff[blockIdx.x] + sh[t];
    if (idx == 0) d_rowptr[0] = 0;
}

__global__ void gstart_kernel() {
    int t = threadIdx.x;
    if (t <= NGg) {
        int lo = 0, hi = Nn;
        while (lo < hi) {
            int mid = (lo + hi) >> 1;
            if (d_batch[mid] < t) lo = mid + 1; else hi = mid;
        }
        d_gstart[t] = lo;
    }
    __syncthreads();
    if (t < NGg) {
        int c = d_gstart[t + 1] - d_gstart[t];
        d_gcntf[t] = (c > 0) ? (float)c : 1.0f;
    }
}

__global__ void dis_cursor_kernel() {
    int i = blockIdx.x * blockDim.x + threadIdx.x;
    if (i < Nn) {
        d_dis[i] = rsqrtf((float)d_deg[i] + 1.0f);
        d_cursor[i] = d_rowptr[i];
    }
}

__global__ void scatter_kernel() {
    int i = blockIdx.x * blockDim.x + threadIdx.x;
    if (i >= Ee) return;
    int s = d_src[i], dd = d_dst[i];
    int pos = atomicAdd(&d_cursor[dd], 1);
    d_col[pos] = s;
    d_w[pos] = d_dis[s] * d_dis[dd];
}

// ---------------- tf32 tensor-core GEMM ----------------
// Y[n,128] = X[n,128] @ W[128,128], fp32 in, tf32 mma, fp32 accum.
// 256 threads (8 warps), 128-row tile. Warp w computes rows w*16..w*16+15, all 128 cols.
// Xs row-major ld=132 (A-frag load conflict-free: bank = 4*qr + qc).
// Ws [k][n]   ld=136 (B-frag load conflict-free: bank = 8*qc + qr + 8t).

#define XS_LD 132
#define WS_LD 136

__device__ __forceinline__ unsigned f2tf32(float v) {
    unsigned o;
    asm("cvt.rna.tf32.f32 %0, %1;" : "=r"(o) : "f"(v));
    return o;
}

#define TF32_GEMM_CORE()                                                          \
    extern __shared__ float sh[];                                                 \
    float* Xs = sh;                                                               \
    float* Ws = sh + 128 * XS_LD;                                                 \
    const int tid = threadIdx.x;                                                  \
    const int row0 = blockIdx.x * 128;                                            \
    _Pragma("unroll")                                                             \
    for (int i = 0; i < 16; i++) {                                                \
        int idx = i * 256 + tid;                                                  \
        int r = idx >> 5;                                                         \
        int c = (idx & 31) * 4;                                                   \
        float4 wv = *(const float4*)&W[r * 128 + c];                              \
        Ws[r * WS_LD + c + 0] = __uint_as_float(f2tf32(wv.x));                    \
        Ws[r * WS_LD + c + 1] = __uint_as_float(f2tf32(wv.y));                    \
        Ws[r * WS_LD + c + 2] = __uint_as_float(f2tf32(wv.z));                    \
        Ws[r * WS_LD + c + 3] = __uint_as_float(f2tf32(wv.w));                    \
        float4 xv = make_float4(0.f, 0.f, 0.f, 0.f);                              \
        if (row0 + r < n) xv = *(const float4*)&X[(size_t)(row0 + r) * 128 + c];  \
        Xs[r * XS_LD + c + 0] = __uint_as_float(f2tf32(xv.x));                    \
        Xs[r * XS_LD + c + 1] = __uint_as_float(f2tf32(xv.y));                    \
        Xs[r * XS_LD + c + 2] = __uint_as_float(f2tf32(xv.z));                    \
        Xs[r * XS_LD + c + 3] = __uint_as_float(f2tf32(xv.w));                    \
    }                                                                             \
    __syncthreads();                                                              \
    const int warp = tid >> 5;                                                    \
    const int lane = tid & 31;                                                    \
    const int qr = lane >> 2;                                                     \
    const int qc = lane & 3;                                                      \
    const int m0 = warp * 16;                                                     \
    float acc[16][4];                                                             \
    _Pragma("unroll")                                                             \
    for (int t = 0; t < 16; t++) {                                                \
        acc[t][0] = 0.f; acc[t][1] = 0.f; acc[t][2] = 0.f; acc[t][3] = 0.f;       \
    }                                                                             \
    _Pragma("unroll 4")                                                           \
    for (int k0 = 0; k0 < 128; k0 += 8) {                                         \
        unsigned a0 = __float_as_uint(Xs[(m0 + qr)     * XS_LD + k0 + qc]);       \
        unsigned a1 = __float_as_uint(Xs[(m0 + qr + 8) * XS_LD + k0 + qc]);       \
        unsigned a2 = __float_as_uint(Xs[(m0 + qr)     * XS_LD + k0 + qc + 4]);   \
        unsigned a3 = __float_as_uint(Xs[(m0 + qr + 8) * XS_LD + k0 + qc + 4]);   \
        _Pragma("unroll")                                                         \
        for (int t = 0; t < 16; t++) {                                            \
            unsigned b0 = __float_as_uint(Ws[(k0 + qc)     * WS_LD + t * 8 + qr]);\
            unsigned b1 = __float_as_uint(Ws[(k0 + qc + 4) * WS_LD + t * 8 + qr]);\
            asm volatile(                                                         \
                "mma.sync.aligned.m16n8k8.row.col.f32.tf32.tf32.f32 "             \
                "{%0,%1,%2,%3}, {%4,%5,%6,%7}, {%8,%9}, {%0,%1,%2,%3};"           \
                : "+f"(acc[t][0]), "+f"(acc[t][1]),                               \
                  "+f"(acc[t][2]), "+f"(acc[t][3])                                \
                : "r"(a0), "r"(a1), "r"(a2), "r"(a3), "r"(b0), "r"(b1));          \
        }                                                                         \
    }                                                                             \
    const int r_lo = row0 + m0 + qr;                                              \
    const int r_hi = r_lo + 8;

// fp16-output GEMM (feeds edge gather)
__global__ __launch_bounds__(256) void gemm_tf32_half_kernel(
    const float* __restrict__ X, const float* __restrict__ W,
    __half* __restrict__ Y, int n) {
    TF32_GEMM_CORE()
    if (r_lo < n) {
#pragma unroll
        for (int t = 0; t < 16; t++)
            *(__half2*)&Y[(size_t)r_lo * 128 + t * 8 + qc * 2] =
                __floats2half2_rn(acc[t][0], acc[t][1]);
    }
    if (r_hi < n) {
#pragma unroll
        for (int t = 0; t < 16; t++)
            *(__half2*)&Y[(size_t)r_hi * 128 + t * 8 + qc * 2] =
                __floats2half2_rn(acc[t][2], acc[t][3]);
    }
}

// final GEMM with fused predictor head:
// out[r] = sigmoid( sum_c relu(acc[r][c]+bp1[c]) * Wp2[c] + bp2 )
__global__ __launch_bounds__(256) void gemm_tf32_head_kernel(
    const float* __restrict__ X, const float* __restrict__ W,
    const float* __restrict__ bp1, const float* __restrict__ Wp2,
    const float* __restrict__ bp2, float* __restrict__ out, int n) {
    TF32_GEMM_CORE()
    float p_lo = 0.f, p_hi = 0.f;
#pragma unroll
    for (int t = 0; t < 16; t++) {
        int c = t * 8 + qc * 2;
        float b0v = bp1[c], b1v = bp1[c + 1];
        float w0v = Wp2[c], w1v = Wp2[c + 1];
        p_lo += fmaxf(acc[t][0] + b0v, 0.f) * w0v + fmaxf(acc[t][1] + b1v, 0.f) * w1v;
        p_hi += fmaxf(acc[t][2] + b0v, 0.f) * w0v + fmaxf(acc[t][3] + b1v, 0.f) * w1v;
    }
    // reduce across the 4 lanes of each row quad (lanes share qr)
    p_lo += __shfl_xor_sync(0xffffffffu, p_lo, 1);
    p_lo += __shfl_xor_sync(0xffffffffu, p_lo, 2);
    p_hi += __shfl_xor_sync(0xffffffffu, p_hi, 1);
    p_hi += __shfl_xor_sync(0xffffffffu, p_hi, 2);
    if (qc == 0) {
        float bb = bp2[0];
        if (r_lo < n) out[r_lo] = 1.f / (1.f + expf(-(p_lo + bb)));
        if (r_hi < n) out[r_hi] = 1.f / (1.f + expf(-(p_hi + bb)));
    }
}

// ---------------- CSR aggregation (fp16 gather, fp32 accumulate) --------------
__global__ void agg_kernel(const __half* __restrict__ T, const float* __restrict__ bias,
                           float* __restrict__ A) {
    int warp = (blockIdx.x * blockDim.x + threadIdx.x) >> 5;
    if (warp >= Nn) return;
    int lane = threadIdx.x & 31;
    int s = d_rowptr[warp], e = d_rowptr[warp + 1];
    float ax = 0.f, ay = 0.f, az = 0.f, aw = 0.f;
    int p = s;
    for (; p + 4 <= e; p += 4) {
        int c0 = d_col[p], c1 = d_col[p + 1], c2 = d_col[p + 2], c3 = d_col[p + 3];
        float w0 = d_w[p], w1 = d_w[p + 1], w2 = d_w[p + 2], w3 = d_w[p + 3];
        uint2 u0 = ((const uint2*)(T + (size_t)c0 * 128))[lane];
        uint2 u1 = ((const uint2*)(T + (size_t)c1 * 128))[lane];
        uint2 u2 = ((const uint2*)(T + (size_t)c2 * 128))[lane];
        uint2 u3 = ((const uint2*)(T + (size_t)c3 * 128))[lane];
        float2 a0 = __half22float2(*(__half2*)&u0.x), b0 = __half22float2(*(__half2*)&u0.y);
        float2 a1 = __half22float2(*(__half2*)&u1.x), b1 = __half22float2(*(__half2*)&u1.y);
        float2 a2 = __half22float2(*(__half2*)&u2.x), b2 = __half22float2(*(__half2*)&u2.y);
        float2 a3 = __half22float2(*(__half2*)&u3.x), b3 = __half22float2(*(__half2*)&u3.y);
        ax += w0 * a0.x + w1 * a1.x + w2 * a2.x + w3 * a3.x;
        ay += w0 * a0.y + w1 * a1.y + w2 * a2.y + w3 * a3.y;
        az += w0 * b0.x + w1 * b1.x + w2 * b2.x + w3 * b3.x;
        aw += w0 * b0.y + w1 * b1.y + w2 * b2.y + w3 * b3.y;
    }
    for (; p < e; p++) {
        int c = d_col[p];
        float w = d_w[p];
        uint2 u = ((const uint2*)(T + (size_t)c * 128))[lane];
        float2 a = __half22float2(*(__half2*)&u.x), b = __half22float2(*(__half2*)&u.y);
        ax += w * a.x; ay += w * a.y; az += w * b.x; aw += w * b.y;
    }
    float ds = d_dis[warp];
    float sl = ds * ds;
    uint2 ut = ((const uint2*)(T + (size_t)warp * 128))[lane];
    float2 ta = __half22float2(*(__half2*)&ut.x), tb = __half22float2(*(__half2*)&ut.y);
    float4 bb = *(const float4*)&bias[lane * 4];
    float4 o;
    o.x = ax + sl * ta.x + bb.x;
    o.y = ay + sl * ta.y + bb.y;
    o.z = az + sl * tb.x + bb.z;
    o.w = aw + sl * tb.y + bb.w;
    *(float4*)&A[(size_t)warp * 128 + lane * 4] = o;
}

// ---------------- GraphNorm: single-pass sum + sumsq reduction ----------------
__global__ void reduce_kernel(const float* __restrict__ A, const float* __restrict__ alpha) {
    int g = blockIdx.x;
    int lane = threadIdx.x & 31;
    int f = blockIdx.y * 32 + lane;
    int sub = threadIdx.x >> 5;  // 0..7
    int s = d_gstart[g], e = d_gstart[g + 1];
    float sum = 0.f, sq = 0.f;
    for (int i = s + sub; i < e; i += 8) {
        float v = A[(size_t)i * 128 + f];
        sum += v; sq += v * v;
    }
    __shared__ float sh1[8][32], sh2[8][32];
    sh1[sub][lane] = sum;
    sh2[sub][lane] = sq;
    __syncthreads();
    if (sub == 0) {
        float t1 = 0.f, t2 = 0.f;
#pragma unroll
        for (int k = 0; k < 8; k++) { t1 += sh1[k][lane]; t2 += sh2[k][lane]; }
        float inv = 1.f / d_gcntf[g];
        float m = t1 * inv;
        float q = t2 * inv;
        float al = alpha[f];
        d_mean[g * 128 + f] = m;
        d_var[g * 128 + f] = q - m * m * al * (2.f - al);
    }
}

// out = [in +] relu((A - alpha*mean) * rsqrt(var+eps) * gamma + beta)
template <int RES>
__global__ void final_kernel(const float* __restrict__ A, const float* __restrict__ in,
                             const float* __restrict__ alpha, const float* __restrict__ gamma,
                             const float* __restrict__ beta, float* __restrict__ out) {
    int idx = blockIdx.x * blockDim.x + threadIdx.x;  // over N*32 float4s
    if (idx >= Nn * 32) return;
    int node = idx >> 5;
    int q = idx & 31;
    int g = d_batch[node];
    float4 a = ((const float4*)A)[idx];
    float4 m = *(const float4*)&d_mean[g * 128 + q * 4];
    float4 vv = *(const float4*)&d_var[g * 128 + q * 4];
    float4 al = *(const float4*)&alpha[q * 4];
    float4 ga = *(const float4*)&gamma[q * 4];
    float4 be = *(const float4*)&beta[q * 4];
    float4 o;
    o.x = fmaxf((a.x - al.x * m.x) * rsqrtf(vv.x + EPSc) * ga.x + be.x, 0.f);
    o.y = fmaxf((a.y - al.y * m.y) * rsqrtf(vv.y + EPSc) * ga.y + be.y, 0.f);
    o.z = fmaxf((a.z - al.z * m.z) * rsqrtf(vv.z + EPSc) * ga.z + be.z, 0.f);
    o.w = fmaxf((a.w - al.w * m.w) * rsqrtf(vv.w + EPSc) * ga.w + be.w, 0.f);
    if (RES) {
        float4 r = ((const float4*)in)[idx];
        o.x += r.x; o.y += r.y; o.z += r.z; o.w += r.w;
    }
    ((float4*)out)[idx] = o;
}

// ---------------- host orchestration ----------------
extern "C" void kernel_launch(void* const* d_in, const int* in_sizes, int n_in,
                              void* d_out, int out_size) {
    const float* x   = (const float*)d_in[0];
    const void*  ei  = d_in[1];
    const void*  bt  = d_in[2];
    const float* W1  = (const float*)d_in[3];
    const float* b1  = (const float*)d_in[4];
    const float* a1  = (const float*)d_in[5];
    const float* g1  = (const float*)d_in[6];
    const float* be1 = (const float*)d_in[7];
    const float* Wm  = (const float*)d_in[8];
    const float* bm  = (const float*)d_in[9];
    const float* am  = (const float*)d_in[10];
    const float* gm  = (const float*)d_in[11];
    const float* bem = (const float*)d_in[12];
    const float* WL  = (const float*)d_in[13];
    const float* bL  = (const float*)d_in[14];
    const float* aL  = (const float*)d_in[15];
    const float* gL  = (const float*)d_in[16];
    const float* beL = (const float*)d_in[17];
    const float* Wp1 = (const float*)d_in[18];
    const float* bp1 = (const float*)d_in[19];
    const float* Wp2 = (const float*)d_in[20];
    const float* bp2 = (const float*)d_in[21];
    float* out = (float*)d_out;

    float *HA, *HB, *A;
    __half* Th;
    cudaGetSymbolAddress((void**)&HA, d_HA);
    cudaGetSymbolAddress((void**)&HB, d_HB);
    cudaGetSymbolAddress((void**)&Th, d_Th);
    cudaGetSymbolAddress((void**)&A,  d_A);

    const int smem = (128 * XS_LD + 128 * WS_LD) * (int)sizeof(float);
    cudaFuncSetAttribute(gemm_tf32_half_kernel, cudaFuncAttributeMaxDynamicSharedMemorySize, smem);
    cudaFuncSetAttribute(gemm_tf32_head_kernel, cudaFuncAttributeMaxDynamicSharedMemorySize, smem);

    // ---- preprocessing ----
    detect_kernel<<<1, 32>>>(ei);
    zero_kernel<<<(Nn + 255) / 256, 256>>>();
    convert_hist_kernel<<<1024, 256>>>(ei, bt);
    bsum_kernel<<<NB_SCAN, 256>>>();
    bscan_kernel<<<1, 256>>>();
    rowptr_kernel<<<NB_SCAN, 256>>>();
    gstart_kernel<<<1, 128>>>();
    dis_cursor_kernel<<<(Nn + 255) / 256, 256>>>();
    scatter_kernel<<<(Ee + 255) / 256, 256>>>();

    const int gemm_grid = (Nn + 127) / 128;
    const int agg_grid  = (Nn * 32 + 255) / 256;
    const int elem_grid = (Nn * 32 + 255) / 256;
    dim3 red_grid(NGg, 4);

    // ---- layer 1: x -> HB ----
    gemm_tf32_half_kernel<<<gemm_grid, 256, smem>>>(x, W1, Th, Nn);
    agg_kernel<<<agg_grid, 256>>>(Th, b1, A);
    reduce_kernel<<<red_grid, 256>>>(A, a1);
    final_kernel<0><<<elem_grid, 256>>>(A, nullptr, a1, g1, be1, HB);

    // ---- mid layer 0 (residual): HB -> HA ----
    gemm_tf32_half_kernel<<<gemm_grid, 256, smem>>>(HB, Wm + 0 * 128 * 128, Th, Nn);
    agg_kernel<<<agg_grid, 256>>>(Th, bm + 0 * 128, A);
    reduce_kernel<<<red_grid, 256>>>(A, am + 0 * 128);
    final_kernel<1><<<elem_grid, 256>>>(A, HB, am + 0 * 128, gm + 0 * 128, bem + 0 * 128, HA);

    // ---- mid layer 1 (residual): HA -> HB ----
    gemm_tf32_half_kernel<<<gemm_grid, 256, smem>>>(HA, Wm + 1 * 128 * 128, Th, Nn);
    agg_kernel<<<agg_grid, 256>>>(Th, bm + 1 * 128, A);
    reduce_kernel<<<red_grid, 256>>>(A, am + 1 * 128);
    final_kernel<1><<<elem_grid, 256>>>(A, HA, am + 1 * 128, gm + 1 * 128, bem + 1 * 128, HB);

    // ---- last layer: HB -> HA ----
    gemm_tf32_half_kernel<<<gemm_grid, 256, smem>>>(HB, WL, Th, Nn);
    agg_kernel<<<agg_grid, 256>>>(Th, bL, A);
    reduce_kernel<<<red_grid, 256>>>(A, aL);
    final_kernel<0><<<elem_grid, 256>>>(A, nullptr, aL, gL, beL, HA);

    // ---- predictor: HA -> out (tf32 GEMM with fused relu-MLP head) ----
    gemm_tf32_head_kernel<<<gemm_grid, 256, smem>>>(HA, Wp1, bp1, Wp2, bp2, out, Nn);
}